// round 7
// baseline (speedup 1.0000x reference)
#include <cuda_runtime.h>

// ---------------- problem constants ----------------
#define BB   1024
#define TT   256
#define HH   256
#define G3   768      // 3*H
#define OUTD 9
#define PRED 16
#define NB   8        // batch rows per block in GRU kernels
#define NBLK (BB/NB)  // 128
#define KIN  265      // OUTD + HH (decoder GRU input width)

typedef unsigned long long u64;

// ---------------- device scratch (static; no allocations allowed) ----------------
__device__ float g_tr[BB*TT*3];          // timestep reprs
__device__ float g_enc_out[BB*TT*HH];    // encoder outputs (268 MB)
__device__ float g_enc_proj[BB*TT*HH];   // enc_proj        (268 MB)
__device__ float g_WhhEncT[HH*G3];       // [k][g]
__device__ float g_WhhDecT[HH*G3];       // [k][g]
__device__ float g_WihDecT[KIN*G3];      // [k][g]
__device__ float g_WtDecT[HH*HH];        // [k][g]
__device__ float g_WtEncT[HH*HH];        // [k][g]
__device__ float g_h[BB*HH];
__device__ float g_q[BB*HH];
__device__ float g_ctx[BB*HH];
__device__ float g_dec_in[BB*OUTD];

// ---------------- packed f32x2 helpers (sm_100+) ----------------
__device__ __forceinline__ u64 pk2(float a, float b){
    u64 r; asm("mov.b64 %0,{%1,%2};" : "=l"(r) : "f"(a), "f"(b)); return r;
}
__device__ __forceinline__ void upk2(u64 v, float& a, float& b){
    asm("mov.b64 {%0,%1},%2;" : "=f"(a), "=f"(b) : "l"(v));
}
__device__ __forceinline__ u64 ffma2(u64 a, u64 b, u64 c){
    u64 d; asm("fma.rn.f32x2 %0,%1,%2,%3;" : "=l"(d) : "l"(a), "l"(b), "l"(c)); return d;
}

// ---------------- fast activations ----------------
__device__ __forceinline__ float fast_sigmoid(float x){
    x = fminf(fmaxf(x, -30.f), 30.f);
    float e = __expf(-x);
    return __fdividef(1.f, 1.f + e);
}
__device__ __forceinline__ float fast_tanh(float x){
    x = fminf(fmaxf(x, -15.f), 15.f);
    float e = __expf(2.f * x);
    return __fdividef(e - 1.f, e + 1.f);
}

// ---------------- weight transposes ----------------
__global__ void prep_weights_kernel(const float* __restrict__ eWhh,
                                    const float* __restrict__ dWhh,
                                    const float* __restrict__ dWih,
                                    const float* __restrict__ Wt){
    int idx = blockIdx.x * 256 + threadIdx.x;
    if (idx < G3*HH){
        int g = idx / HH, k = idx - g*HH;
        g_WhhEncT[k*G3 + g] = eWhh[idx];
        g_WhhDecT[k*G3 + g] = dWhh[idx];
    }
    if (idx < G3*KIN){
        int g = idx / KIN, k = idx - g*KIN;
        g_WihDecT[k*G3 + g] = dWih[idx];
    }
    if (idx < HH*HH){
        int g = idx / HH, k = idx - g*HH;
        g_WtDecT[k*HH + g] = Wt[g*(2*HH) + k];
        g_WtEncT[k*HH + g] = Wt[g*(2*HH) + HH + k];
    }
}

// ---------------- agent attention -> timestep reprs ----------------
__global__ void __launch_bounds__(256) agent_attn_kernel(const float* __restrict__ x,
        const float* __restrict__ Wa, const float* __restrict__ ba,
        const float* __restrict__ va){
    __shared__ float sW[HH*3], sb[HH], sv[HH];
    int tid = threadIdx.x;
    for (int idx = tid; idx < HH*3; idx += 256) sW[idx] = Wa[idx];
    sb[tid] = ba[tid];
    sv[tid] = va[tid];
    __syncthreads();
    int bt = blockIdx.x * 256 + tid;
    float xf[9];
    #pragma unroll
    for (int f = 0; f < 9; f++) xf[f] = x[bt*9 + f];
    float s0 = 0.f, s1 = 0.f, s2 = 0.f;
    for (int h = 0; h < HH; h++){
        float w0 = sW[h*3], w1 = sW[h*3+1], w2 = sW[h*3+2];
        float bb_ = sb[h], v = sv[h];
        s0 += v * fast_tanh(w0*xf[0] + w1*xf[1] + w2*xf[2] + bb_);
        s1 += v * fast_tanh(w0*xf[3] + w1*xf[4] + w2*xf[5] + bb_);
        s2 += v * fast_tanh(w0*xf[6] + w1*xf[7] + w2*xf[8] + bb_);
    }
    float m  = fmaxf(s0, fmaxf(s1, s2));
    float e0 = __expf(s0 - m), e1 = __expf(s1 - m), e2 = __expf(s2 - m);
    float inv = __fdividef(1.f, e0 + e1 + e2);
    float a0 = e0*inv, a1 = e1*inv, a2 = e2*inv;
    #pragma unroll
    for (int f = 0; f < 3; f++)
        g_tr[bt*3 + f] = a0*xf[f] + a1*xf[3+f] + a2*xf[6+f];
}

// ---------------- encoder GRU (persistent over t; f32x2 inner loop) ----------------
__global__ void __launch_bounds__(256) encoder_kernel(const float* __restrict__ Wih,
        const float* __restrict__ bih, const float* __restrict__ bhh){
    const int b0 = blockIdx.x * NB;
    const int j  = threadIdx.x;                 // h-dim owned by this thread
    __shared__ alignas(16) float h_sm[HH*NB];   // [k*NB + i]
    __shared__ float xs[NB*3];                  // [i*3 + f]

    for (int idx = j; idx < HH*NB; idx += 256) h_sm[idx] = 0.f;

    float wR[3], wZ[3], wN[3];
    #pragma unroll
    for (int f = 0; f < 3; f++){
        wR[f] = Wih[j*3 + f];
        wZ[f] = Wih[(j+256)*3 + f];
        wN[f] = Wih[(j+512)*3 + f];
    }
    const float bR  = bih[j]     + bhh[j];
    const float bZ  = bih[j+256] + bhh[j+256];
    const float biN = bih[j+512];
    const float bhN = bhh[j+512];
    const float* __restrict__ Wcol = g_WhhEncT + j;

    for (int t = 0; t < TT; t++){
        if (j < NB*3){
            int i = j / 3, f = j - i*3;
            xs[j] = g_tr[((b0+i)*TT + t)*3 + f];
        }
        __syncthreads();

        u64 aR[4], aZ[4], aN[4];
        float iN[8];
        #pragma unroll
        for (int p = 0; p < 4; p++){
            int i0 = 2*p, i1 = 2*p + 1;
            float r0 = bR + wR[0]*xs[i0*3] + wR[1]*xs[i0*3+1] + wR[2]*xs[i0*3+2];
            float r1 = bR + wR[0]*xs[i1*3] + wR[1]*xs[i1*3+1] + wR[2]*xs[i1*3+2];
            float z0 = bZ + wZ[0]*xs[i0*3] + wZ[1]*xs[i0*3+1] + wZ[2]*xs[i0*3+2];
            float z1 = bZ + wZ[0]*xs[i1*3] + wZ[1]*xs[i1*3+1] + wZ[2]*xs[i1*3+2];
            aR[p] = pk2(r0, r1);
            aZ[p] = pk2(z0, z1);
            aN[p] = pk2(bhN, bhN);
            iN[i0] = biN + wN[0]*xs[i0*3] + wN[1]*xs[i0*3+1] + wN[2]*xs[i0*3+2];
            iN[i1] = biN + wN[0]*xs[i1*3] + wN[1]*xs[i1*3+1] + wN[2]*xs[i1*3+2];
        }

        #pragma unroll 4
        for (int k = 0; k < HH; k++){
            float wr = Wcol[k*G3];
            float wz = Wcol[k*G3 + 256];
            float wn = Wcol[k*G3 + 512];
            u64 wr2 = pk2(wr, wr), wz2 = pk2(wz, wz), wn2 = pk2(wn, wn);
            const u64* hp = (const u64*)(h_sm + k*NB);
            #pragma unroll
            for (int p = 0; p < 4; p++){
                u64 h2 = hp[p];
                aR[p] = ffma2(wr2, h2, aR[p]);
                aZ[p] = ffma2(wz2, h2, aZ[p]);
                aN[p] = ffma2(wn2, h2, aN[p]);
            }
        }

        float hnew[8];
        #pragma unroll
        for (int p = 0; p < 4; p++){
            float r0,r1,z0,z1,n0,n1;
            upk2(aR[p], r0, r1);
            upk2(aZ[p], z0, z1);
            upk2(aN[p], n0, n1);
            float h0 = h_sm[j*NB + 2*p];
            float h1 = h_sm[j*NB + 2*p + 1];
            float rr0 = fast_sigmoid(r0), rr1 = fast_sigmoid(r1);
            float zz0 = fast_sigmoid(z0), zz1 = fast_sigmoid(z1);
            float nn0 = fast_tanh(iN[2*p]   + rr0*n0);
            float nn1 = fast_tanh(iN[2*p+1] + rr1*n1);
            hnew[2*p]   = nn0 + zz0*(h0 - nn0);
            hnew[2*p+1] = nn1 + zz1*(h1 - nn1);
        }
        __syncthreads();
        #pragma unroll
        for (int i = 0; i < NB; i++){
            h_sm[j*NB + i] = hnew[i];
            g_enc_out[((b0+i)*TT + t)*HH + j] = hnew[i];
        }
    }
    __syncthreads();
    #pragma unroll
    for (int i = 0; i < NB; i++)
        g_h[(b0+i)*HH + j] = h_sm[j*NB + i];
}

// ---------------- enc_proj = enc_out @ WtEncT  (tiled fp32 GEMM) ----------------
__global__ void __launch_bounds__(256) encproj_gemm_kernel(){
    __shared__ float As[64][17];
    __shared__ float Bs[16][64];
    const int tid = threadIdx.x;
    const int tx = tid & 15, ty = tid >> 4;
    const int bm = blockIdx.x, bn = blockIdx.y;
    float acc[4][4] = {};
    const int arow = tid >> 2, acol = (tid & 3) << 2;
    const int brow = tid >> 4, bcol = (tid & 15) << 2;
    const float* Ap = g_enc_out + (bm*64 + arow)*HH + acol;
    const float* Bp = g_WtEncT + brow*HH + bn*64 + bcol;
    for (int k0 = 0; k0 < HH; k0 += 16){
        float4 av = *reinterpret_cast<const float4*>(Ap + k0);
        As[arow][acol]   = av.x;
        As[arow][acol+1] = av.y;
        As[arow][acol+2] = av.z;
        As[arow][acol+3] = av.w;
        float4 bv = *reinterpret_cast<const float4*>(Bp + k0*HH);
        *reinterpret_cast<float4*>(&Bs[brow][bcol]) = bv;
        __syncthreads();
        #pragma unroll
        for (int kk = 0; kk < 16; kk++){
            float a[4], b[4];
            #pragma unroll
            for (int i = 0; i < 4; i++){ a[i] = As[ty*4+i][kk]; b[i] = Bs[kk][tx*4+i]; }
            #pragma unroll
            for (int i = 0; i < 4; i++)
                #pragma unroll
                for (int jj = 0; jj < 4; jj++) acc[i][jj] += a[i]*b[jj];
        }
        __syncthreads();
    }
    float* Cp = g_enc_proj + (bm*64 + ty*4)*HH + bn*64 + tx*4;
    #pragma unroll
    for (int i = 0; i < 4; i++)
        #pragma unroll
        for (int jj = 0; jj < 4; jj++) Cp[i*HH + jj] = acc[i][jj];
}

// ---------------- decoder init ----------------
__global__ void dec_init_kernel(const float* __restrict__ x){
    int idx = blockIdx.x * 256 + threadIdx.x;
    if (idx < BB*OUTD){
        int b = idx / OUTD, f = idx - b*OUTD;
        g_dec_in[idx] = x[(b*TT + (TT-1))*9 + f];
    }
}

// q0 = h_enc @ WtDec^T + bt
__global__ void __launch_bounds__(256) compute_q0_kernel(const float* __restrict__ bt){
    const int b0 = blockIdx.x * NB;
    const int j = threadIdx.x;
    __shared__ float hs[NB*HH];   // [i*HH + k]
    for (int idx = j; idx < NB*HH; idx += 256) hs[idx] = g_h[b0*HH + idx];
    __syncthreads();
    float qa[NB];
    float btj = bt[j];
    #pragma unroll
    for (int i = 0; i < NB; i++) qa[i] = btj;
    const float* Wq = g_WtDecT + j;
    #pragma unroll 4
    for (int k = 0; k < HH; k++){
        float w = Wq[k*HH];
        #pragma unroll
        for (int i = 0; i < NB; i++) qa[i] += w * hs[i*HH + k];
    }
    #pragma unroll
    for (int i = 0; i < NB; i++) g_q[(b0+i)*HH + j] = qa[i];
}

// ---------------- decoder temporal attention + context (one block per b) ----------------
__global__ void __launch_bounds__(256) dec_attn_kernel(const float* __restrict__ vt){
    const int b = blockIdx.x, tid = threadIdx.x, w = tid >> 5, l = tid & 31;
    __shared__ float qs[HH], vs[HH], sc[TT], rb1[8], rb2[8];
    qs[tid] = g_q[b*HH + tid];
    vs[tid] = vt[tid];
    __syncthreads();
    for (int t = w; t < TT; t += 8){
        const float* ep = g_enc_proj + (b*TT + t)*HH;
        float a = 0.f;
        #pragma unroll
        for (int u = 0; u < 8; u++){
            int h = l + u*32;
            a += vs[h] * fast_tanh(ep[h] + qs[h]);
        }
        #pragma unroll
        for (int o = 16; o; o >>= 1) a += __shfl_xor_sync(0xffffffffu, a, o);
        if (l == 0) sc[t] = a;
    }
    __syncthreads();
    // softmax over T=256 (one value per thread)
    float v = sc[tid];
    float m = v;
    #pragma unroll
    for (int o = 16; o; o >>= 1) m = fmaxf(m, __shfl_xor_sync(0xffffffffu, m, o));
    if (l == 0) rb1[w] = m;
    __syncthreads();
    m = rb1[0];
    #pragma unroll
    for (int i = 1; i < 8; i++) m = fmaxf(m, rb1[i]);
    float e = __expf(v - m);
    float s = e;
    #pragma unroll
    for (int o = 16; o; o >>= 1) s += __shfl_xor_sync(0xffffffffu, s, o);
    if (l == 0) rb2[w] = s;
    __syncthreads();
    s = 0.f;
    #pragma unroll
    for (int i = 0; i < 8; i++) s += rb2[i];
    sc[tid] = e * __fdividef(1.f, s);
    __syncthreads();
    // context
    float c = 0.f;
    const float* eo = g_enc_out + b*TT*HH + tid;
    #pragma unroll 8
    for (int t2 = 0; t2 < TT; t2++) c += sc[t2] * eo[t2*HH];
    g_ctx[b*HH + tid] = c;
}

// ---------------- decoder GRU + prediction head + next-step q ----------------
__global__ void __launch_bounds__(256) dec_gru_kernel(const float* __restrict__ bih,
        const float* __restrict__ bhh, const float* __restrict__ bt,
        const float* __restrict__ Wfc, const float* __restrict__ bfc,
        float* __restrict__ out, int step){
    const int b0 = blockIdx.x * NB;
    const int j  = threadIdx.x;
    __shared__ alignas(16) float in_sm[KIN*NB];  // [k*NB + i]
    __shared__ alignas(16) float h_sm[HH*NB];    // [k*NB + i]
    __shared__ float hn_sm[NB*HH];               // [i*HH + k]

    for (int idx = j; idx < KIN*NB; idx += 256){
        int k = idx / NB, i = idx - k*NB;
        in_sm[idx] = (k < OUTD) ? g_dec_in[(b0+i)*OUTD + k]
                                : g_ctx[(b0+i)*HH + (k - OUTD)];
    }
    for (int idx = j; idx < HH*NB; idx += 256){
        int k = idx / NB, i = idx - k*NB;
        h_sm[idx] = g_h[(b0+i)*HH + k];
    }
    __syncthreads();

    u64 aR[4], aZ[4], aNi[4], aNh[4];
    {
        float bR = bih[j] + bhh[j];
        float bZ = bih[j+256] + bhh[j+256];
        float bi = bih[j+512], bh = bhh[j+512];
        #pragma unroll
        for (int p = 0; p < 4; p++){
            aR[p]  = pk2(bR, bR);
            aZ[p]  = pk2(bZ, bZ);
            aNi[p] = pk2(bi, bi);
            aNh[p] = pk2(bh, bh);
        }
    }
    const float* Wi = g_WihDecT + j;
    #pragma unroll 4
    for (int k = 0; k < KIN; k++){
        float wr = Wi[k*G3], wz = Wi[k*G3 + 256], wn = Wi[k*G3 + 512];
        u64 wr2 = pk2(wr, wr), wz2 = pk2(wz, wz), wn2 = pk2(wn, wn);
        const u64* ip = (const u64*)(in_sm + k*NB);
        #pragma unroll
        for (int p = 0; p < 4; p++){
            u64 v = ip[p];
            aR[p]  = ffma2(wr2, v, aR[p]);
            aZ[p]  = ffma2(wz2, v, aZ[p]);
            aNi[p] = ffma2(wn2, v, aNi[p]);
        }
    }
    const float* Wh = g_WhhDecT + j;
    #pragma unroll 4
    for (int k = 0; k < HH; k++){
        float wr = Wh[k*G3], wz = Wh[k*G3 + 256], wn = Wh[k*G3 + 512];
        u64 wr2 = pk2(wr, wr), wz2 = pk2(wz, wz), wn2 = pk2(wn, wn);
        const u64* hp = (const u64*)(h_sm + k*NB);
        #pragma unroll
        for (int p = 0; p < 4; p++){
            u64 v = hp[p];
            aR[p]  = ffma2(wr2, v, aR[p]);
            aZ[p]  = ffma2(wz2, v, aZ[p]);
            aNh[p] = ffma2(wn2, v, aNh[p]);
        }
    }

    float hnew[8];
    #pragma unroll
    for (int p = 0; p < 4; p++){
        float r0,r1,z0,z1,ni0,ni1,nh0,nh1;
        upk2(aR[p],  r0,  r1);
        upk2(aZ[p],  z0,  z1);
        upk2(aNi[p], ni0, ni1);
        upk2(aNh[p], nh0, nh1);
        float h0 = h_sm[j*NB + 2*p];
        float h1 = h_sm[j*NB + 2*p + 1];
        float rr0 = fast_sigmoid(r0), rr1 = fast_sigmoid(r1);
        float zz0 = fast_sigmoid(z0), zz1 = fast_sigmoid(z1);
        float nn0 = fast_tanh(ni0 + rr0*nh0);
        float nn1 = fast_tanh(ni1 + rr1*nh1);
        hnew[2*p]   = nn0 + zz0*(h0 - nn0);
        hnew[2*p+1] = nn1 + zz1*(h1 - nn1);
    }
    #pragma unroll
    for (int i = 0; i < NB; i++){
        g_h[(b0+i)*HH + j] = hnew[i];
        hn_sm[i*HH + j]    = hnew[i];
    }
    __syncthreads();

    // q for next step
    {
        float qa[NB];
        float btj = bt[j];
        #pragma unroll
        for (int i = 0; i < NB; i++) qa[i] = btj;
        const float* Wq = g_WtDecT + j;
        #pragma unroll 4
        for (int k = 0; k < HH; k++){
            float w = Wq[k*HH];
            #pragma unroll
            for (int i = 0; i < NB; i++) qa[i] += w * hn_sm[i*HH + k];
        }
        #pragma unroll
        for (int i = 0; i < NB; i++) g_q[(b0+i)*HH + j] = qa[i];
    }

    // prediction head: 8 rows x 9 outputs
    if (j < NB*OUTD){
        int i = j / OUTD, o = j - i*OUTD;
        float d = bfc[o];
        const float* wf = Wfc + o*HH;
        const float* hv = hn_sm + i*HH;
        #pragma unroll 4
        for (int k = 0; k < HH; k++) d += wf[k] * hv[k];
        out[((b0+i)*PRED + step)*OUTD + o] = d;
        g_dec_in[(b0+i)*OUTD + o] = d;
    }
}

// ---------------- launcher ----------------
extern "C" void kernel_launch(void* const* d_in, const int* in_sizes, int n_in,
                              void* d_out, int out_size){
    const float* x    = (const float*)d_in[0];
    const float* Wa   = (const float*)d_in[1];
    const float* ba   = (const float*)d_in[2];
    const float* va   = (const float*)d_in[3];
    const float* eWih = (const float*)d_in[4];
    const float* eWhh = (const float*)d_in[5];
    const float* ebih = (const float*)d_in[6];
    const float* ebhh = (const float*)d_in[7];
    const float* dWih = (const float*)d_in[8];
    const float* dWhh = (const float*)d_in[9];
    const float* dbih = (const float*)d_in[10];
    const float* dbhh = (const float*)d_in[11];
    const float* Wt   = (const float*)d_in[12];
    const float* bt   = (const float*)d_in[13];
    const float* vt   = (const float*)d_in[14];
    const float* Wfc  = (const float*)d_in[15];
    const float* bfc  = (const float*)d_in[16];
    float* out = (float*)d_out;

    prep_weights_kernel<<<(G3*KIN + 255)/256, 256>>>(eWhh, dWhh, dWih, Wt);
    agent_attn_kernel<<<BB*TT/256, 256>>>(x, Wa, ba, va);
    encoder_kernel<<<NBLK, 256>>>(eWih, ebih, ebhh);
    encproj_gemm_kernel<<<dim3(BB*TT/64, HH/64), 256>>>();
    dec_init_kernel<<<(BB*OUTD + 255)/256, 256>>>(x);
    compute_q0_kernel<<<NBLK, 256>>>(bt);
    for (int p = 0; p < PRED; p++){
        dec_attn_kernel<<<BB, 256>>>(vt);
        dec_gru_kernel<<<NBLK, 256>>>(dbih, dbhh, bt, Wfc, bfc, out, p);
    }
}

// round 12
// speedup vs baseline: 1.4753x; 1.4753x over previous
#include <cuda_runtime.h>
#include <cuda_bf16.h>

// ---------------- problem constants ----------------
#define BB   1024
#define TT   256
#define HH   256
#define G3   768      // 3*H
#define OUTD 9
#define PRED 16
#define NB   8        // batch rows per block in GRU kernels
#define NBLK (BB/NB)  // 128
#define KIN  265      // OUTD + HH (decoder GRU input width)

typedef unsigned long long u64;

// ---------------- device scratch (static; no allocations allowed) ----------------
__device__ float g_tr[BB*TT*3];                     // timestep reprs
__device__ __nv_bfloat16 g_enc_out_bf[BB*TT*HH];    // encoder outputs (bf16, 134 MB)
__device__ __nv_bfloat16 g_enc_proj_bf[BB*TT*HH];   // enc_proj (bf16, 134 MB)
__device__ float g_WhhEncT[HH*G3];       // [k][g]
__device__ float g_WhhDecT[HH*G3];       // [k][g]
__device__ float g_WihDecT[KIN*G3];      // [k][g]
__device__ float g_WtDecT[HH*HH];        // [k][g]
__device__ float g_WtEncT[HH*HH];        // [k][g]
__device__ float g_h[BB*HH];
__device__ float g_q[BB*HH];
__device__ float g_ctx[BB*HH];
__device__ float g_dec_in[BB*OUTD];

// ---------------- packed f32x2 helpers (fma form proven on this toolchain) -----
__device__ __forceinline__ u64 pk2(float a, float b){
    u64 r; asm("mov.b64 %0,{%1,%2};" : "=l"(r) : "f"(a), "f"(b)); return r;
}
__device__ __forceinline__ void upk2(u64 v, float& a, float& b){
    asm("mov.b64 {%0,%1},%2;" : "=f"(a), "=f"(b) : "l"(v));
}
__device__ __forceinline__ u64 ffma2(u64 a, u64 b, u64 c){
    u64 d; asm("fma.rn.f32x2 %0,%1,%2,%3;" : "=l"(d) : "l"(a), "l"(b), "l"(c)); return d;
}

// ---------------- fast activations ----------------
__device__ __forceinline__ float fast_sigmoid(float x){
    x = fminf(fmaxf(x, -30.f), 30.f);
    float e = __expf(-x);
    return __fdividef(1.f, 1.f + e);
}
__device__ __forceinline__ float fast_tanh(float x){
    x = fminf(fmaxf(x, -15.f), 15.f);
    float e = __expf(2.f * x);
    return __fdividef(e - 1.f, e + 1.f);
}

// ---------------- weight transposes ----------------
__global__ void prep_weights_kernel(const float* __restrict__ eWhh,
                                    const float* __restrict__ dWhh,
                                    const float* __restrict__ dWih,
                                    const float* __restrict__ Wt){
    int idx = blockIdx.x * 256 + threadIdx.x;
    if (idx < G3*HH){
        int g = idx / HH, k = idx - g*HH;
        g_WhhEncT[k*G3 + g] = eWhh[idx];
        g_WhhDecT[k*G3 + g] = dWhh[idx];
    }
    if (idx < G3*KIN){
        int g = idx / KIN, k = idx - g*KIN;
        g_WihDecT[k*G3 + g] = dWih[idx];
    }
    if (idx < HH*HH){
        int g = idx / HH, k = idx - g*HH;
        g_WtDecT[k*HH + g] = Wt[g*(2*HH) + k];
        g_WtEncT[k*HH + g] = Wt[g*(2*HH) + HH + k];
    }
}

// ---------------- agent attention -> timestep reprs ----------------
__global__ void __launch_bounds__(256) agent_attn_kernel(const float* __restrict__ x,
        const float* __restrict__ Wa, const float* __restrict__ ba,
        const float* __restrict__ va){
    __shared__ float sW[HH*3], sb[HH], sv[HH];
    int tid = threadIdx.x;
    for (int idx = tid; idx < HH*3; idx += 256) sW[idx] = Wa[idx];
    sb[tid] = ba[tid];
    sv[tid] = va[tid];
    __syncthreads();
    int bt = blockIdx.x * 256 + tid;
    float xf[9];
    #pragma unroll
    for (int f = 0; f < 9; f++) xf[f] = x[bt*9 + f];
    float s0 = 0.f, s1 = 0.f, s2 = 0.f;
    for (int h = 0; h < HH; h++){
        float w0 = sW[h*3], w1 = sW[h*3+1], w2 = sW[h*3+2];
        float bb_ = sb[h], v = sv[h];
        s0 += v * fast_tanh(w0*xf[0] + w1*xf[1] + w2*xf[2] + bb_);
        s1 += v * fast_tanh(w0*xf[3] + w1*xf[4] + w2*xf[5] + bb_);
        s2 += v * fast_tanh(w0*xf[6] + w1*xf[7] + w2*xf[8] + bb_);
    }
    float m  = fmaxf(s0, fmaxf(s1, s2));
    float e0 = __expf(s0 - m), e1 = __expf(s1 - m), e2 = __expf(s2 - m);
    float inv = __fdividef(1.f, e0 + e1 + e2);
    float a0 = e0*inv, a1 = e1*inv, a2 = e2*inv;
    #pragma unroll
    for (int f = 0; f < 3; f++)
        g_tr[bt*3 + f] = a0*xf[f] + a1*xf[3+f] + a2*xf[6+f];
}

// ---------------- encoder GRU: 512 threads, 2-way k-split ----------------
// thread (j, s): j = h-dim owned, s = which half of the k-reduction.
// s=1 writes partial accumulators to smem; s=0 combines + activations.
__global__ void __launch_bounds__(512) encoder_kernel(const float* __restrict__ Wih,
        const float* __restrict__ bih, const float* __restrict__ bhh){
    const int b0  = blockIdx.x * NB;
    const int tid = threadIdx.x;
    const int j   = tid & 255;
    const int s   = tid >> 8;
    __shared__ alignas(16) float h_sm[HH*NB];   // [k*NB + i]
    __shared__ float xs[NB*3];                  // [i*3 + f]
    __shared__ alignas(16) u64 ps[256*12];      // s=1 partials (24 KB)

    for (int idx = tid; idx < HH*NB; idx += 512) h_sm[idx] = 0.f;

    float wR[3] = {0,0,0}, wZ[3] = {0,0,0}, wN[3] = {0,0,0};
    float bR = 0.f, bZ = 0.f, biN = 0.f, bhN = 0.f;
    if (s == 0){
        #pragma unroll
        for (int f = 0; f < 3; f++){
            wR[f] = Wih[j*3 + f];
            wZ[f] = Wih[(j+256)*3 + f];
            wN[f] = Wih[(j+512)*3 + f];
        }
        bR  = bih[j]     + bhh[j];
        bZ  = bih[j+256] + bhh[j+256];
        biN = bih[j+512];
        bhN = bhh[j+512];
    }
    const float* __restrict__ Wcol = g_WhhEncT + j + (s << 7) * G3;  // k offset s*128
    const int kb = s << 7;
    float hnew[8];

    for (int t = 0; t < TT; t++){
        if (tid < NB*3){
            int i = tid / 3, f = tid - i*3;
            xs[tid] = g_tr[((b0+i)*TT + t)*3 + f];
        }
        __syncthreads();

        u64 aR[4], aZ[4], aN[4];
        float iN[8];
        if (s == 0){
            #pragma unroll
            for (int p = 0; p < 4; p++){
                int i0 = 2*p, i1 = 2*p + 1;
                float r0 = bR + wR[0]*xs[i0*3] + wR[1]*xs[i0*3+1] + wR[2]*xs[i0*3+2];
                float r1 = bR + wR[0]*xs[i1*3] + wR[1]*xs[i1*3+1] + wR[2]*xs[i1*3+2];
                float z0 = bZ + wZ[0]*xs[i0*3] + wZ[1]*xs[i0*3+1] + wZ[2]*xs[i0*3+2];
                float z1 = bZ + wZ[0]*xs[i1*3] + wZ[1]*xs[i1*3+1] + wZ[2]*xs[i1*3+2];
                aR[p] = pk2(r0, r1);
                aZ[p] = pk2(z0, z1);
                aN[p] = pk2(bhN, bhN);
                iN[i0] = biN + wN[0]*xs[i0*3] + wN[1]*xs[i0*3+1] + wN[2]*xs[i0*3+2];
                iN[i1] = biN + wN[0]*xs[i1*3] + wN[1]*xs[i1*3+1] + wN[2]*xs[i1*3+2];
            }
        } else {
            #pragma unroll
            for (int p = 0; p < 4; p++){ aR[p] = 0ull; aZ[p] = 0ull; aN[p] = 0ull; }
        }

        #pragma unroll 4
        for (int k = 0; k < 128; k++){
            float wr = Wcol[k*G3];
            float wz = Wcol[k*G3 + 256];
            float wn = Wcol[k*G3 + 512];
            u64 wr2 = pk2(wr, wr), wz2 = pk2(wz, wz), wn2 = pk2(wn, wn);
            const u64* hp = (const u64*)(h_sm + (kb + k)*NB);
            #pragma unroll
            for (int p = 0; p < 4; p++){
                u64 h2 = hp[p];
                aR[p] = ffma2(wr2, h2, aR[p]);
                aZ[p] = ffma2(wz2, h2, aZ[p]);
                aN[p] = ffma2(wn2, h2, aN[p]);
            }
        }

        if (s == 1){
            u64* pp = ps + j*12;
            #pragma unroll
            for (int p = 0; p < 4; p++){
                pp[p]     = aR[p];
                pp[4 + p] = aZ[p];
                pp[8 + p] = aN[p];
            }
        }
        __syncthreads();

        if (s == 0){
            const u64* pp = ps + j*12;
            #pragma unroll
            for (int p = 0; p < 4; p++){
                float r0,r1,z0,z1,n0,n1;
                float pr0,pr1,pz0,pz1,pn0,pn1;
                upk2(aR[p], r0, r1);
                upk2(aZ[p], z0, z1);
                upk2(aN[p], n0, n1);
                upk2(pp[p],     pr0, pr1);
                upk2(pp[4 + p], pz0, pz1);
                upk2(pp[8 + p], pn0, pn1);
                r0 += pr0; r1 += pr1;
                z0 += pz0; z1 += pz1;
                n0 += pn0; n1 += pn1;
                float h0 = h_sm[j*NB + 2*p];
                float h1 = h_sm[j*NB + 2*p + 1];
                float rr0 = fast_sigmoid(r0), rr1 = fast_sigmoid(r1);
                float zz0 = fast_sigmoid(z0), zz1 = fast_sigmoid(z1);
                float nn0 = fast_tanh(iN[2*p]   + rr0*n0);
                float nn1 = fast_tanh(iN[2*p+1] + rr1*n1);
                hnew[2*p]   = nn0 + zz0*(h0 - nn0);
                hnew[2*p+1] = nn1 + zz1*(h1 - nn1);
            }
            #pragma unroll
            for (int i = 0; i < NB; i++){
                h_sm[j*NB + i] = hnew[i];
                g_enc_out_bf[((b0+i)*TT + t)*HH + j] = __float2bfloat16(hnew[i]);
            }
        }
        // next iteration's first __syncthreads() orders h_sm writes vs reads
    }
    if (s == 0){
        #pragma unroll
        for (int i = 0; i < NB; i++)
            g_h[(b0+i)*HH + j] = hnew[i];
    }
}

// ---------------- enc_proj(bf16) = enc_out(bf16) @ WtEncT(fp32) ----------------
__global__ void __launch_bounds__(256) encproj_gemm_kernel(){
    __shared__ float As[64][17];
    __shared__ float Bs[16][64];
    const int tid = threadIdx.x;
    const int tx = tid & 15, ty = tid >> 4;
    const int bm = blockIdx.x, bn = blockIdx.y;
    float acc[4][4] = {};
    const int arow = tid >> 2, acol = (tid & 3) << 2;   // 4 bf16 per thread
    const int brow = tid >> 4, bcol = (tid & 15) << 2;
    const __nv_bfloat16* Ap = g_enc_out_bf + (bm*64 + arow)*HH + acol;
    const float* Bp = g_WtEncT + brow*HH + bn*64 + bcol;
    for (int k0 = 0; k0 < HH; k0 += 16){
        uint2 av = *reinterpret_cast<const uint2*>(Ap + k0);
        __nv_bfloat162 alo = *reinterpret_cast<__nv_bfloat162*>(&av.x);
        __nv_bfloat162 ahi = *reinterpret_cast<__nv_bfloat162*>(&av.y);
        float2 f0 = __bfloat1622float2(alo);
        float2 f1 = __bfloat1622float2(ahi);
        As[arow][acol]   = f0.x;
        As[arow][acol+1] = f0.y;
        As[arow][acol+2] = f1.x;
        As[arow][acol+3] = f1.y;
        float4 bv = *reinterpret_cast<const float4*>(Bp + k0*HH);
        *reinterpret_cast<float4*>(&Bs[brow][bcol]) = bv;
        __syncthreads();
        #pragma unroll
        for (int kk = 0; kk < 16; kk++){
            float a[4], b[4];
            #pragma unroll
            for (int i = 0; i < 4; i++){ a[i] = As[ty*4+i][kk]; b[i] = Bs[kk][tx*4+i]; }
            #pragma unroll
            for (int i = 0; i < 4; i++)
                #pragma unroll
                for (int jj = 0; jj < 4; jj++) acc[i][jj] += a[i]*b[jj];
        }
        __syncthreads();
    }
    __nv_bfloat16* Cp = g_enc_proj_bf + (bm*64 + ty*4)*HH + bn*64 + tx*4;
    #pragma unroll
    for (int i = 0; i < 4; i++){
        __nv_bfloat162 c0 = __floats2bfloat162_rn(acc[i][0], acc[i][1]);
        __nv_bfloat162 c1 = __floats2bfloat162_rn(acc[i][2], acc[i][3]);
        *reinterpret_cast<__nv_bfloat162*>(Cp + i*HH)     = c0;
        *reinterpret_cast<__nv_bfloat162*>(Cp + i*HH + 2) = c1;
    }
}

// ---------------- decoder init ----------------
__global__ void dec_init_kernel(const float* __restrict__ x){
    int idx = blockIdx.x * 256 + threadIdx.x;
    if (idx < BB*OUTD){
        int b = idx / OUTD, f = idx - b*OUTD;
        g_dec_in[idx] = x[(b*TT + (TT-1))*9 + f];
    }
}

// q0 = h_enc @ WtDec^T + bt
__global__ void __launch_bounds__(256) compute_q0_kernel(const float* __restrict__ bt){
    const int b0 = blockIdx.x * NB;
    const int j = threadIdx.x;
    __shared__ float hs[NB*HH];   // [i*HH + k]
    for (int idx = j; idx < NB*HH; idx += 256) hs[idx] = g_h[b0*HH + idx];
    __syncthreads();
    float qa[NB];
    float btj = bt[j];
    #pragma unroll
    for (int i = 0; i < NB; i++) qa[i] = btj;
    const float* Wq = g_WtDecT + j;
    #pragma unroll 4
    for (int k = 0; k < HH; k++){
        float w = Wq[k*HH];
        #pragma unroll
        for (int i = 0; i < NB; i++) qa[i] += w * hs[i*HH + k];
    }
    #pragma unroll
    for (int i = 0; i < NB; i++) g_q[(b0+i)*HH + j] = qa[i];
}

// ---------------- decoder temporal attention + context (bf16 streams) ----------------
__global__ void __launch_bounds__(256) dec_attn_kernel(const float* __restrict__ vt){
    const int b = blockIdx.x, tid = threadIdx.x, w = tid >> 5, l = tid & 31;
    __shared__ alignas(16) float qs[HH];
    __shared__ alignas(16) float vs[HH];
    __shared__ float sc[TT], rb1[8], rb2[8];
    qs[tid] = g_q[b*HH + tid];
    vs[tid] = vt[tid];
    __syncthreads();

    // per-lane q/v slice (h = l*8 .. l*8+7) held in registers; conflict-free LDS.128
    float4 qA = *reinterpret_cast<float4*>(qs + l*8);
    float4 qB = *reinterpret_cast<float4*>(qs + l*8 + 4);
    float4 vA = *reinterpret_cast<float4*>(vs + l*8);
    float4 vB = *reinterpret_cast<float4*>(vs + l*8 + 4);
    float qr[8] = {qA.x,qA.y,qA.z,qA.w,qB.x,qB.y,qB.z,qB.w};
    float vr[8] = {vA.x,vA.y,vA.z,vA.w,vB.x,vB.y,vB.z,vB.w};

    for (int t = w; t < TT; t += 8){
        const __nv_bfloat16* ep = g_enc_proj_bf + (size_t)(b*TT + t)*HH + l*8;
        uint4 pv = *reinterpret_cast<const uint4*>(ep);
        float2 e0 = __bfloat1622float2(*reinterpret_cast<__nv_bfloat162*>(&pv.x));
        float2 e1 = __bfloat1622float2(*reinterpret_cast<__nv_bfloat162*>(&pv.y));
        float2 e2 = __bfloat1622float2(*reinterpret_cast<__nv_bfloat162*>(&pv.z));
        float2 e3 = __bfloat1622float2(*reinterpret_cast<__nv_bfloat162*>(&pv.w));
        float ef[8] = {e0.x,e0.y,e1.x,e1.y,e2.x,e2.y,e3.x,e3.y};
        float a = 0.f;
        #pragma unroll
        for (int u = 0; u < 8; u++)
            a += vr[u] * fast_tanh(ef[u] + qr[u]);
        #pragma unroll
        for (int o = 16; o; o >>= 1) a += __shfl_xor_sync(0xffffffffu, a, o);
        if (l == 0) sc[t] = a;
    }
    __syncthreads();
    // softmax over T=256 (one value per thread)
    float v = sc[tid];
    float m = v;
    #pragma unroll
    for (int o = 16; o; o >>= 1) m = fmaxf(m, __shfl_xor_sync(0xffffffffu, m, o));
    if (l == 0) rb1[w] = m;
    __syncthreads();
    m = rb1[0];
    #pragma unroll
    for (int i = 1; i < 8; i++) m = fmaxf(m, rb1[i]);
    float e = __expf(v - m);
    float s = e;
    #pragma unroll
    for (int o = 16; o; o >>= 1) s += __shfl_xor_sync(0xffffffffu, s, o);
    if (l == 0) rb2[w] = s;
    __syncthreads();
    s = 0.f;
    #pragma unroll
    for (int i = 0; i < 8; i++) s += rb2[i];
    sc[tid] = e * __fdividef(1.f, s);
    __syncthreads();
    // context
    float c = 0.f;
    const __nv_bfloat16* eo = g_enc_out_bf + (size_t)b*TT*HH + tid;
    #pragma unroll 8
    for (int t2 = 0; t2 < TT; t2++) c += sc[t2] * __bfloat162float(eo[t2*HH]);
    g_ctx[b*HH + tid] = c;
}

// ---------------- decoder GRU + prediction head + next-step q ----------------
__global__ void __launch_bounds__(256) dec_gru_kernel(const float* __restrict__ bih,
        const float* __restrict__ bhh, const float* __restrict__ bt,
        const float* __restrict__ Wfc, const float* __restrict__ bfc,
        float* __restrict__ out, int step){
    const int b0 = blockIdx.x * NB;
    const int j  = threadIdx.x;
    __shared__ alignas(16) float in_sm[KIN*NB];  // [k*NB + i]
    __shared__ alignas(16) float h_sm[HH*NB];    // [k*NB + i]
    __shared__ float hn_sm[NB*HH];               // [i*HH + k]

    for (int idx = j; idx < KIN*NB; idx += 256){
        int k = idx / NB, i = idx - k*NB;
        in_sm[idx] = (k < OUTD) ? g_dec_in[(b0+i)*OUTD + k]
                                : g_ctx[(b0+i)*HH + (k - OUTD)];
    }
    for (int idx = j; idx < HH*NB; idx += 256){
        int k = idx / NB, i = idx - k*NB;
        h_sm[idx] = g_h[(b0+i)*HH + k];
    }
    __syncthreads();

    u64 aR[4], aZ[4], aNi[4], aNh[4];
    {
        float bR = bih[j] + bhh[j];
        float bZ = bih[j+256] + bhh[j+256];
        float bi = bih[j+512], bh = bhh[j+512];
        #pragma unroll
        for (int p = 0; p < 4; p++){
            aR[p]  = pk2(bR, bR);
            aZ[p]  = pk2(bZ, bZ);
            aNi[p] = pk2(bi, bi);
            aNh[p] = pk2(bh, bh);
        }
    }
    const float* Wi = g_WihDecT + j;
    #pragma unroll 4
    for (int k = 0; k < KIN; k++){
        float wr = Wi[k*G3], wz = Wi[k*G3 + 256], wn = Wi[k*G3 + 512];
        u64 wr2 = pk2(wr, wr), wz2 = pk2(wz, wz), wn2 = pk2(wn, wn);
        const u64* ip = (const u64*)(in_sm + k*NB);
        #pragma unroll
        for (int p = 0; p < 4; p++){
            u64 v = ip[p];
            aR[p]  = ffma2(wr2, v, aR[p]);
            aZ[p]  = ffma2(wz2, v, aZ[p]);
            aNi[p] = ffma2(wn2, v, aNi[p]);
        }
    }
    const float* Wh = g_WhhDecT + j;
    #pragma unroll 4
    for (int k = 0; k < HH; k++){
        float wr = Wh[k*G3], wz = Wh[k*G3 + 256], wn = Wh[k*G3 + 512];
        u64 wr2 = pk2(wr, wr), wz2 = pk2(wz, wz), wn2 = pk2(wn, wn);
        const u64* hp = (const u64*)(h_sm + k*NB);
        #pragma unroll
        for (int p = 0; p < 4; p++){
            u64 v = hp[p];
            aR[p]  = ffma2(wr2, v, aR[p]);
            aZ[p]  = ffma2(wz2, v, aZ[p]);
            aNh[p] = ffma2(wn2, v, aNh[p]);
        }
    }

    float hnew[8];
    #pragma unroll
    for (int p = 0; p < 4; p++){
        float r0,r1,z0,z1,ni0,ni1,nh0,nh1;
        upk2(aR[p],  r0,  r1);
        upk2(aZ[p],  z0,  z1);
        upk2(aNi[p], ni0, ni1);
        upk2(aNh[p], nh0, nh1);
        float h0 = h_sm[j*NB + 2*p];
        float h1 = h_sm[j*NB + 2*p + 1];
        float rr0 = fast_sigmoid(r0), rr1 = fast_sigmoid(r1);
        float zz0 = fast_sigmoid(z0), zz1 = fast_sigmoid(z1);
        float nn0 = fast_tanh(ni0 + rr0*nh0);
        float nn1 = fast_tanh(ni1 + rr1*nh1);
        hnew[2*p]   = nn0 + zz0*(h0 - nn0);
        hnew[2*p+1] = nn1 + zz1*(h1 - nn1);
    }
    #pragma unroll
    for (int i = 0; i < NB; i++){
        g_h[(b0+i)*HH + j] = hnew[i];
        hn_sm[i*HH + j]    = hnew[i];
    }
    __syncthreads();

    // q for next step
    {
        float qa[NB];
        float btj = bt[j];
        #pragma unroll
        for (int i = 0; i < NB; i++) qa[i] = btj;
        const float* Wq = g_WtDecT + j;
        #pragma unroll 4
        for (int k = 0; k < HH; k++){
            float w = Wq[k*HH];
            #pragma unroll
            for (int i = 0; i < NB; i++) qa[i] += w * hn_sm[i*HH + k];
        }
        #pragma unroll
        for (int i = 0; i < NB; i++) g_q[(b0+i)*HH + j] = qa[i];
    }

    // prediction head: 8 rows x 9 outputs
    if (j < NB*OUTD){
        int i = j / OUTD, o = j - i*OUTD;
        float d = bfc[o];
        const float* wf = Wfc + o*HH;
        const float* hv = hn_sm + i*HH;
        #pragma unroll 4
        for (int k = 0; k < HH; k++) d += wf[k] * hv[k];
        out[((b0+i)*PRED + step)*OUTD + o] = d;
        g_dec_in[(b0+i)*OUTD + o] = d;
    }
}

// ---------------- launcher ----------------
extern "C" void kernel_launch(void* const* d_in, const int* in_sizes, int n_in,
                              void* d_out, int out_size){
    const float* x    = (const float*)d_in[0];
    const float* Wa   = (const float*)d_in[1];
    const float* ba   = (const float*)d_in[2];
    const float* va   = (const float*)d_in[3];
    const float* eWih = (const float*)d_in[4];
    const float* eWhh = (const float*)d_in[5];
    const float* ebih = (const float*)d_in[6];
    const float* ebhh = (const float*)d_in[7];
    const float* dWih = (const float*)d_in[8];
    const float* dWhh = (const float*)d_in[9];
    const float* dbih = (const float*)d_in[10];
    const float* dbhh = (const float*)d_in[11];
    const float* Wt   = (const float*)d_in[12];
    const float* bt   = (const float*)d_in[13];
    const float* vt   = (const float*)d_in[14];
    const float* Wfc  = (const float*)d_in[15];
    const float* bfc  = (const float*)d_in[16];
    float* out = (float*)d_out;

    prep_weights_kernel<<<(G3*KIN + 255)/256, 256>>>(eWhh, dWhh, dWih, Wt);
    agent_attn_kernel<<<BB*TT/256, 256>>>(x, Wa, ba, va);
    encoder_kernel<<<NBLK, 512>>>(eWih, ebih, ebhh);
    encproj_gemm_kernel<<<dim3(BB*TT/64, HH/64), 256>>>();
    dec_init_kernel<<<(BB*OUTD + 255)/256, 256>>>(x);
    compute_q0_kernel<<<NBLK, 256>>>(bt);
    for (int p = 0; p < PRED; p++){
        dec_attn_kernel<<<BB, 256>>>(vt);
        dec_gru_kernel<<<NBLK, 256>>>(dbih, dbhh, bt, Wfc, bfc, out, p);
    }
}

// round 14
// speedup vs baseline: 1.7594x; 1.1926x over previous
#include <cuda_runtime.h>
#include <cuda_bf16.h>

// ---------------- problem constants ----------------
#define BB   1024
#define TT   256
#define HH   256
#define G3   768      // 3*H
#define OUTD 9
#define PRED 16
#define NB   8        // batch rows per block in GRU kernels
#define NBLK (BB/NB)  // 128
#define KIN  265      // OUTD + HH (decoder GRU input width)

typedef unsigned long long u64;

// ---------------- device scratch (static; no allocations allowed) ----------------
__device__ float g_tr[BB*TT*3];                     // timestep reprs
__device__ __nv_bfloat16 g_enc_out_bf[BB*TT*HH];    // encoder outputs (bf16)
__device__ __nv_bfloat16 g_enc_proj_bf[BB*TT*HH];   // enc_proj (bf16)
__device__ float g_WhhEnc4[(HH/4)*G3*4];  // [k/4][g][4] -> LDG.128 = 4 k-weights of gate g
__device__ float g_WhhDecT[HH*G3];        // [k][g]
__device__ float g_WihDecT[KIN*G3];       // [k][g]
__device__ float g_WtDecT[HH*HH];         // [k][g]
__device__ float g_WtEncT[HH*HH];         // [k][g]
__device__ float g_h[BB*HH];
__device__ float g_q[BB*HH];
__device__ float g_ctx[BB*HH];
__device__ float g_dec_in[BB*OUTD];

// ---------------- packed f32x2 helpers ----------------
__device__ __forceinline__ u64 pk2(float a, float b){
    u64 r; asm("mov.b64 %0,{%1,%2};" : "=l"(r) : "f"(a), "f"(b)); return r;
}
__device__ __forceinline__ void upk2(u64 v, float& a, float& b){
    asm("mov.b64 {%0,%1},%2;" : "=f"(a), "=f"(b) : "l"(v));
}
__device__ __forceinline__ u64 ffma2(u64 a, u64 b, u64 c){
    u64 d; asm("fma.rn.f32x2 %0,%1,%2,%3;" : "=l"(d) : "l"(a), "l"(b), "l"(c)); return d;
}

// ---------------- fast activations ----------------
__device__ __forceinline__ float fast_sigmoid(float x){
    x = fminf(fmaxf(x, -30.f), 30.f);
    float e = __expf(-x);
    return __fdividef(1.f, 1.f + e);
}
__device__ __forceinline__ float fast_tanh(float x){
    x = fminf(fmaxf(x, -15.f), 15.f);
    float e = __expf(2.f * x);
    return __fdividef(e - 1.f, e + 1.f);
}

// ---------------- weight transposes ----------------
__global__ void prep_weights_kernel(const float* __restrict__ eWhh,
                                    const float* __restrict__ dWhh,
                                    const float* __restrict__ dWih,
                                    const float* __restrict__ Wt){
    int idx = blockIdx.x * 256 + threadIdx.x;
    if (idx < G3*HH){
        int g = idx / HH, k = idx - g*HH;
        g_WhhEnc4[(k >> 2)*(G3*4) + g*4 + (k & 3)] = eWhh[idx];
        g_WhhDecT[k*G3 + g] = dWhh[idx];
    }
    if (idx < G3*KIN){
        int g = idx / KIN, k = idx - g*KIN;
        g_WihDecT[k*G3 + g] = dWih[idx];
    }
    if (idx < HH*HH){
        int g = idx / HH, k = idx - g*HH;
        g_WtDecT[k*HH + g] = Wt[g*(2*HH) + k];
        g_WtEncT[k*HH + g] = Wt[g*(2*HH) + HH + k];
    }
}

// ---------------- agent attention -> timestep reprs ----------------
__global__ void __launch_bounds__(256) agent_attn_kernel(const float* __restrict__ x,
        const float* __restrict__ Wa, const float* __restrict__ ba,
        const float* __restrict__ va){
    __shared__ float sW[HH*3], sb[HH], sv[HH];
    int tid = threadIdx.x;
    for (int idx = tid; idx < HH*3; idx += 256) sW[idx] = Wa[idx];
    sb[tid] = ba[tid];
    sv[tid] = va[tid];
    __syncthreads();
    int bt = blockIdx.x * 256 + tid;
    float xf[9];
    #pragma unroll
    for (int f = 0; f < 9; f++) xf[f] = x[bt*9 + f];
    float s0 = 0.f, s1 = 0.f, s2 = 0.f;
    for (int h = 0; h < HH; h++){
        float w0 = sW[h*3], w1 = sW[h*3+1], w2 = sW[h*3+2];
        float bb_ = sb[h], v = sv[h];
        s0 += v * fast_tanh(w0*xf[0] + w1*xf[1] + w2*xf[2] + bb_);
        s1 += v * fast_tanh(w0*xf[3] + w1*xf[4] + w2*xf[5] + bb_);
        s2 += v * fast_tanh(w0*xf[6] + w1*xf[7] + w2*xf[8] + bb_);
    }
    float m  = fmaxf(s0, fmaxf(s1, s2));
    float e0 = __expf(s0 - m), e1 = __expf(s1 - m), e2 = __expf(s2 - m);
    float inv = __fdividef(1.f, e0 + e1 + e2);
    float a0 = e0*inv, a1 = e1*inv, a2 = e2*inv;
    #pragma unroll
    for (int f = 0; f < 3; f++)
        g_tr[bt*3 + f] = a0*xf[f] + a1*xf[3+f] + a2*xf[6+f];
}

// ---------------- encoder GRU: 512 threads, 2-way k-split, vector loads --------
// thread (j, s): j = gate column owned (h-dim), s = which k-half it reduces.
// Weights: LDG.128 gives 4 consecutive-k weights of gate row (2 f32x2 pairs).
// h_sm [i][k]: LDS.128 broadcast gives h[k..k+3] for batch row i.
// Accumulate k-pairs into u64 accums; horizontal add at the end of the k-loop.
__global__ void __launch_bounds__(512) encoder_kernel(const float* __restrict__ Wih,
        const float* __restrict__ bih, const float* __restrict__ bhh){
    const int b0  = blockIdx.x * NB;
    const int tid = threadIdx.x;
    const int j   = tid & 255;
    const int s   = tid >> 8;
    __shared__ alignas(16) float h_sm[NB][HH];   // [i][k]  8.2 KB
    __shared__ float xs[NB*3];                   // [i*3 + f]
    __shared__ float ps[256][25];                // s=1 reduced partials (24 used)

    for (int idx = tid; idx < NB*HH; idx += 512)
        h_sm[idx >> 8][idx & 255] = 0.f;

    float wR[3] = {0,0,0}, wZ[3] = {0,0,0}, wN[3] = {0,0,0};
    float bR = 0.f, bZ = 0.f, biN = 0.f, bhN = 0.f;
    if (s == 0){
        #pragma unroll
        for (int f = 0; f < 3; f++){
            wR[f] = Wih[j*3 + f];
            wZ[f] = Wih[(j+256)*3 + f];
            wN[f] = Wih[(j+512)*3 + f];
        }
        bR  = bih[j]     + bhh[j];
        bZ  = bih[j+256] + bhh[j+256];
        biN = bih[j+512];
        bhN = bhh[j+512];
    }
    const int w0base = s << 5;   // first k/4 slab for this half (32 slabs each)
    float hnew[8];

    for (int t = 0; t < TT; t++){
        if (tid < NB*3){
            int i = tid / 3, f = tid - i*3;
            xs[tid] = g_tr[((b0+i)*TT + t)*3 + f];
        }
        __syncthreads();   // barrier A: xs ready; h_sm(t-1) writes visible

        u64 aR[8], aZ[8], aN[8];
        #pragma unroll
        for (int i = 0; i < 8; i++){ aR[i] = 0ull; aZ[i] = 0ull; aN[i] = 0ull; }

        #pragma unroll 4
        for (int w = 0; w < 32; w++){
            const int slab = w0base + w;                 // k = slab*4 .. slab*4+3
            const ulonglong2* wq =
                (const ulonglong2*)(g_WhhEnc4 + (size_t)slab*(G3*4));
            ulonglong2 wr = wq[j];
            ulonglong2 wz = wq[j + 256];
            ulonglong2 wn = wq[j + 512];
            #pragma unroll
            for (int i = 0; i < 8; i++){
                ulonglong2 h2 = ((const ulonglong2*)(&h_sm[i][0]))[slab & 63];
                aR[i] = ffma2(wr.x, h2.x, aR[i]);
                aR[i] = ffma2(wr.y, h2.y, aR[i]);
                aZ[i] = ffma2(wz.x, h2.x, aZ[i]);
                aZ[i] = ffma2(wz.y, h2.y, aZ[i]);
                aN[i] = ffma2(wn.x, h2.x, aN[i]);
                aN[i] = ffma2(wn.y, h2.y, aN[i]);
            }
        }

        if (s == 1){
            #pragma unroll
            for (int i = 0; i < 8; i++){
                float lo, hi;
                upk2(aR[i], lo, hi); ps[j][i]      = lo + hi;
                upk2(aZ[i], lo, hi); ps[j][8 + i]  = lo + hi;
                upk2(aN[i], lo, hi); ps[j][16 + i] = lo + hi;
            }
        }
        __syncthreads();   // barrier B: partials ready; all h_sm reads done

        if (s == 0){
            #pragma unroll
            for (int i = 0; i < 8; i++){
                float lo, hi;
                float x0 = xs[i*3], x1 = xs[i*3+1], x2 = xs[i*3+2];
                upk2(aR[i], lo, hi);
                float r = lo + hi + ps[j][i]      + bR + wR[0]*x0 + wR[1]*x1 + wR[2]*x2;
                upk2(aZ[i], lo, hi);
                float z = lo + hi + ps[j][8 + i]  + bZ + wZ[0]*x0 + wZ[1]*x1 + wZ[2]*x2;
                upk2(aN[i], lo, hi);
                float nh = lo + hi + ps[j][16 + i] + bhN;
                float ni = biN + wN[0]*x0 + wN[1]*x1 + wN[2]*x2;
                float h_old = h_sm[i][j];
                float rr = fast_sigmoid(r);
                float zz = fast_sigmoid(z);
                float nn = fast_tanh(ni + rr*nh);
                hnew[i] = nn + zz*(h_old - nn);
            }
            #pragma unroll
            for (int i = 0; i < 8; i++){
                h_sm[i][j] = hnew[i];
                g_enc_out_bf[((b0+i)*TT + t)*HH + j] = __float2bfloat16(hnew[i]);
            }
        }
        // next iteration's barrier A orders h_sm writes vs s=1 reads
    }
    if (s == 0){
        #pragma unroll
        for (int i = 0; i < NB; i++)
            g_h[(b0+i)*HH + j] = hnew[i];
    }
}

// ---------------- enc_proj(bf16) = enc_out(bf16) @ WtEncT(fp32) ----------------
// As stored k-major (transposed) so the inner loop is 2x LDS.128 + 16 FFMA.
__global__ void __launch_bounds__(256) encproj_gemm_kernel(){
    __shared__ alignas(16) float AsT[16][68];   // [kk][row], stride 68 keeps 16B align
    __shared__ alignas(16) float Bs[16][64];
    const int tid = threadIdx.x;
    const int tx = tid & 15, ty = tid >> 4;
    const int bm = blockIdx.x, bn = blockIdx.y;
    float acc[4][4] = {};
    const int arow = tid >> 2, acol = (tid & 3) << 2;   // 4 bf16 per thread
    const int brow = tid >> 4, bcol = (tid & 15) << 2;
    const __nv_bfloat16* Ap = g_enc_out_bf + (bm*64 + arow)*HH + acol;
    const float* Bp = g_WtEncT + brow*HH + bn*64 + bcol;
    for (int k0 = 0; k0 < HH; k0 += 16){
        uint2 av = *reinterpret_cast<const uint2*>(Ap + k0);
        __nv_bfloat162 alo = *reinterpret_cast<__nv_bfloat162*>(&av.x);
        __nv_bfloat162 ahi = *reinterpret_cast<__nv_bfloat162*>(&av.y);
        float2 f0 = __bfloat1622float2(alo);
        float2 f1 = __bfloat1622float2(ahi);
        AsT[acol  ][arow] = f0.x;
        AsT[acol+1][arow] = f0.y;
        AsT[acol+2][arow] = f1.x;
        AsT[acol+3][arow] = f1.y;
        float4 bv = *reinterpret_cast<const float4*>(Bp + k0*HH);
        *reinterpret_cast<float4*>(&Bs[brow][bcol]) = bv;
        __syncthreads();
        #pragma unroll
        for (int kk = 0; kk < 16; kk++){
            float4 a4 = *reinterpret_cast<float4*>(&AsT[kk][ty*4]);
            float4 b4 = *reinterpret_cast<float4*>(&Bs[kk][tx*4]);
            float a[4] = {a4.x, a4.y, a4.z, a4.w};
            float b[4] = {b4.x, b4.y, b4.z, b4.w};
            #pragma unroll
            for (int i = 0; i < 4; i++)
                #pragma unroll
                for (int jj = 0; jj < 4; jj++) acc[i][jj] += a[i]*b[jj];
        }
        __syncthreads();
    }
    __nv_bfloat16* Cp = g_enc_proj_bf + (bm*64 + ty*4)*HH + bn*64 + tx*4;
    #pragma unroll
    for (int i = 0; i < 4; i++){
        __nv_bfloat162 c0 = __floats2bfloat162_rn(acc[i][0], acc[i][1]);
        __nv_bfloat162 c1 = __floats2bfloat162_rn(acc[i][2], acc[i][3]);
        *reinterpret_cast<__nv_bfloat162*>(Cp + i*HH)     = c0;
        *reinterpret_cast<__nv_bfloat162*>(Cp + i*HH + 2) = c1;
    }
}

// ---------------- decoder init ----------------
__global__ void dec_init_kernel(const float* __restrict__ x){
    int idx = blockIdx.x * 256 + threadIdx.x;
    if (idx < BB*OUTD){
        int b = idx / OUTD, f = idx - b*OUTD;
        g_dec_in[idx] = x[(b*TT + (TT-1))*9 + f];
    }
}

// q0 = h_enc @ WtDec^T + bt
__global__ void __launch_bounds__(256) compute_q0_kernel(const float* __restrict__ bt){
    const int b0 = blockIdx.x * NB;
    const int j = threadIdx.x;
    __shared__ float hs[NB*HH];   // [i*HH + k]
    for (int idx = j; idx < NB*HH; idx += 256) hs[idx] = g_h[b0*HH + idx];
    __syncthreads();
    float qa[NB];
    float btj = bt[j];
    #pragma unroll
    for (int i = 0; i < NB; i++) qa[i] = btj;
    const float* Wq = g_WtDecT + j;
    #pragma unroll 4
    for (int k = 0; k < HH; k++){
        float w = Wq[k*HH];
        #pragma unroll
        for (int i = 0; i < NB; i++) qa[i] += w * hs[i*HH + k];
    }
    #pragma unroll
    for (int i = 0; i < NB; i++) g_q[(b0+i)*HH + j] = qa[i];
}

// ---------------- decoder temporal attention + context (bf16 streams) ----------------
__global__ void __launch_bounds__(256) dec_attn_kernel(const float* __restrict__ vt){
    const int b = blockIdx.x, tid = threadIdx.x, w = tid >> 5, l = tid & 31;
    __shared__ alignas(16) float qs[HH];
    __shared__ alignas(16) float vs[HH];
    __shared__ float sc[TT], rb1[8], rb2[8];
    qs[tid] = g_q[b*HH + tid];
    vs[tid] = vt[tid];
    __syncthreads();

    float4 qA = *reinterpret_cast<float4*>(qs + l*8);
    float4 qB = *reinterpret_cast<float4*>(qs + l*8 + 4);
    float4 vA = *reinterpret_cast<float4*>(vs + l*8);
    float4 vB = *reinterpret_cast<float4*>(vs + l*8 + 4);
    float qr[8] = {qA.x,qA.y,qA.z,qA.w,qB.x,qB.y,qB.z,qB.w};
    float vr[8] = {vA.x,vA.y,vA.z,vA.w,vB.x,vB.y,vB.z,vB.w};

    for (int t = w; t < TT; t += 8){
        const __nv_bfloat16* ep = g_enc_proj_bf + (size_t)(b*TT + t)*HH + l*8;
        uint4 pv = *reinterpret_cast<const uint4*>(ep);
        float2 e0 = __bfloat1622float2(*reinterpret_cast<__nv_bfloat162*>(&pv.x));
        float2 e1 = __bfloat1622float2(*reinterpret_cast<__nv_bfloat162*>(&pv.y));
        float2 e2 = __bfloat1622float2(*reinterpret_cast<__nv_bfloat162*>(&pv.z));
        float2 e3 = __bfloat1622float2(*reinterpret_cast<__nv_bfloat162*>(&pv.w));
        float ef[8] = {e0.x,e0.y,e1.x,e1.y,e2.x,e2.y,e3.x,e3.y};
        float a = 0.f;
        #pragma unroll
        for (int u = 0; u < 8; u++)
            a += vr[u] * fast_tanh(ef[u] + qr[u]);
        #pragma unroll
        for (int o = 16; o; o >>= 1) a += __shfl_xor_sync(0xffffffffu, a, o);
        if (l == 0) sc[t] = a;
    }
    __syncthreads();
    float v = sc[tid];
    float m = v;
    #pragma unroll
    for (int o = 16; o; o >>= 1) m = fmaxf(m, __shfl_xor_sync(0xffffffffu, m, o));
    if (l == 0) rb1[w] = m;
    __syncthreads();
    m = rb1[0];
    #pragma unroll
    for (int i = 1; i < 8; i++) m = fmaxf(m, rb1[i]);
    float e = __expf(v - m);
    float s = e;
    #pragma unroll
    for (int o = 16; o; o >>= 1) s += __shfl_xor_sync(0xffffffffu, s, o);
    if (l == 0) rb2[w] = s;
    __syncthreads();
    s = 0.f;
    #pragma unroll
    for (int i = 0; i < 8; i++) s += rb2[i];
    sc[tid] = e * __fdividef(1.f, s);
    __syncthreads();
    float c = 0.f;
    const __nv_bfloat16* eo = g_enc_out_bf + (size_t)b*TT*HH + tid;
    #pragma unroll 8
    for (int t2 = 0; t2 < TT; t2++) c += sc[t2] * __bfloat162float(eo[t2*HH]);
    g_ctx[b*HH + tid] = c;
}

// ---------------- decoder GRU + prediction head + next-step q ----------------
__global__ void __launch_bounds__(256) dec_gru_kernel(const float* __restrict__ bih,
        const float* __restrict__ bhh, const float* __restrict__ bt,
        const float* __restrict__ Wfc, const float* __restrict__ bfc,
        float* __restrict__ out, int step){
    const int b0 = blockIdx.x * NB;
    const int j  = threadIdx.x;
    __shared__ alignas(16) float in_sm[KIN*NB];  // [k*NB + i]
    __shared__ alignas(16) float h_sm[HH*NB];    // [k*NB + i]
    __shared__ float hn_sm[NB*HH];               // [i*HH + k]

    for (int idx = j; idx < KIN*NB; idx += 256){
        int k = idx / NB, i = idx - k*NB;
        in_sm[idx] = (k < OUTD) ? g_dec_in[(b0+i)*OUTD + k]
                                : g_ctx[(b0+i)*HH + (k - OUTD)];
    }
    for (int idx = j; idx < HH*NB; idx += 256){
        int k = idx / NB, i = idx - k*NB;
        h_sm[idx] = g_h[(b0+i)*HH + k];
    }
    __syncthreads();

    u64 aR[4], aZ[4], aNi[4], aNh[4];
    {
        float bR = bih[j] + bhh[j];
        float bZ = bih[j+256] + bhh[j+256];
        float bi = bih[j+512], bh = bhh[j+512];
        #pragma unroll
        for (int p = 0; p < 4; p++){
            aR[p]  = pk2(bR, bR);
            aZ[p]  = pk2(bZ, bZ);
            aNi[p] = pk2(bi, bi);
            aNh[p] = pk2(bh, bh);
        }
    }
    const float* Wi = g_WihDecT + j;
    #pragma unroll 4
    for (int k = 0; k < KIN; k++){
        float wr = Wi[k*G3], wz = Wi[k*G3 + 256], wn = Wi[k*G3 + 512];
        u64 wr2 = pk2(wr, wr), wz2 = pk2(wz, wz), wn2 = pk2(wn, wn);
        const u64* ip = (const u64*)(in_sm + k*NB);
        #pragma unroll
        for (int p = 0; p < 4; p++){
            u64 v = ip[p];
            aR[p]  = ffma2(wr2, v, aR[p]);
            aZ[p]  = ffma2(wz2, v, aZ[p]);
            aNi[p] = ffma2(wn2, v, aNi[p]);
        }
    }
    const float* Wh = g_WhhDecT + j;
    #pragma unroll 4
    for (int k = 0; k < HH; k++){
        float wr = Wh[k*G3], wz = Wh[k*G3 + 256], wn = Wh[k*G3 + 512];
        u64 wr2 = pk2(wr, wr), wz2 = pk2(wz, wz), wn2 = pk2(wn, wn);
        const u64* hp = (const u64*)(h_sm + k*NB);
        #pragma unroll
        for (int p = 0; p < 4; p++){
            u64 v = hp[p];
            aR[p]  = ffma2(wr2, v, aR[p]);
            aZ[p]  = ffma2(wz2, v, aZ[p]);
            aNh[p] = ffma2(wn2, v, aNh[p]);
        }
    }

    float hnew[8];
    #pragma unroll
    for (int p = 0; p < 4; p++){
        float r0,r1,z0,z1,ni0,ni1,nh0,nh1;
        upk2(aR[p],  r0,  r1);
        upk2(aZ[p],  z0,  z1);
        upk2(aNi[p], ni0, ni1);
        upk2(aNh[p], nh0, nh1);
        float h0 = h_sm[j*NB + 2*p];
        float h1 = h_sm[j*NB + 2*p + 1];
        float rr0 = fast_sigmoid(r0), rr1 = fast_sigmoid(r1);
        float zz0 = fast_sigmoid(z0), zz1 = fast_sigmoid(z1);
        float nn0 = fast_tanh(ni0 + rr0*nh0);
        float nn1 = fast_tanh(ni1 + rr1*nh1);
        hnew[2*p]   = nn0 + zz0*(h0 - nn0);
        hnew[2*p+1] = nn1 + zz1*(h1 - nn1);
    }
    #pragma unroll
    for (int i = 0; i < NB; i++){
        g_h[(b0+i)*HH + j] = hnew[i];
        hn_sm[i*HH + j]    = hnew[i];
    }
    __syncthreads();

    // q for next step
    {
        float qa[NB];
        float btj = bt[j];
        #pragma unroll
        for (int i = 0; i < NB; i++) qa[i] = btj;
        const float* Wq = g_WtDecT + j;
        #pragma unroll 4
        for (int k = 0; k < HH; k++){
            float w = Wq[k*HH];
            #pragma unroll
            for (int i = 0; i < NB; i++) qa[i] += w * hn_sm[i*HH + k];
        }
        #pragma unroll
        for (int i = 0; i < NB; i++) g_q[(b0+i)*HH + j] = qa[i];
    }

    // prediction head: 8 rows x 9 outputs
    if (j < NB*OUTD){
        int i = j / OUTD, o = j - i*OUTD;
        float d = bfc[o];
        const float* wf = Wfc + o*HH;
        const float* hv = hn_sm + i*HH;
        #pragma unroll 4
        for (int k = 0; k < HH; k++) d += wf[k] * hv[k];
        out[((b0+i)*PRED + step)*OUTD + o] = d;
        g_dec_in[(b0+i)*OUTD + o] = d;
    }
}

// ---------------- launcher ----------------
extern "C" void kernel_launch(void* const* d_in, const int* in_sizes, int n_in,
                              void* d_out, int out_size){
    const float* x    = (const float*)d_in[0];
    const float* Wa   = (const float*)d_in[1];
    const float* ba   = (const float*)d_in[2];
    const float* va   = (const float*)d_in[3];
    const float* eWih = (const float*)d_in[4];
    const float* eWhh = (const float*)d_in[5];
    const float* ebih = (const float*)d_in[6];
    const float* ebhh = (const float*)d_in[7];
    const float* dWih = (const float*)d_in[8];
    const float* dWhh = (const float*)d_in[9];
    const float* dbih = (const float*)d_in[10];
    const float* dbhh = (const float*)d_in[11];
    const float* Wt   = (const float*)d_in[12];
    const float* bt   = (const float*)d_in[13];
    const float* vt   = (const float*)d_in[14];
    const float* Wfc  = (const float*)d_in[15];
    const float* bfc  = (const float*)d_in[16];
    float* out = (float*)d_out;

    prep_weights_kernel<<<(G3*KIN + 255)/256, 256>>>(eWhh, dWhh, dWih, Wt);
    agent_attn_kernel<<<BB*TT/256, 256>>>(x, Wa, ba, va);
    encoder_kernel<<<NBLK, 512>>>(eWih, ebih, ebhh);
    encproj_gemm_kernel<<<dim3(BB*TT/64, HH/64), 256>>>();
    dec_init_kernel<<<(BB*OUTD + 255)/256, 256>>>(x);
    compute_q0_kernel<<<NBLK, 256>>>(bt);
    for (int p = 0; p < PRED; p++){
        dec_attn_kernel<<<BB, 256>>>(vt);
        dec_gru_kernel<<<NBLK, 256>>>(dbih, dbhh, bt, Wfc, bfc, out, p);
    }
}

// round 17
// speedup vs baseline: 1.8190x; 1.0339x over previous
#include <cuda_runtime.h>
#include <cuda_bf16.h>

// ---------------- problem constants ----------------
#define BB   1024
#define TT   256
#define HH   256
#define G3   768      // 3*H
#define OUTD 9
#define PRED 16
#define NB   8        // batch rows per block in GRU kernels
#define NBLK (BB/NB)  // 128
#define KIN  265      // OUTD + HH (decoder GRU input width)

typedef unsigned long long u64;

// ---------------- device scratch (static; no allocations allowed) ----------------
__device__ float g_tr[BB*TT*3];                     // timestep reprs
__device__ __nv_bfloat16 g_enc_out_bf[BB*TT*HH];    // encoder outputs (bf16)
__device__ __nv_bfloat16 g_enc_proj_bf[BB*TT*HH];   // enc_proj (bf16)
__device__ float g_WhhEnc4[(HH/4)*G3*4];  // [k/4][g][4] -> LDG.128 = 4 k-weights of gate g
__device__ float g_WhhDecT[HH*G3];        // [k][g]
__device__ float g_WihDecT[KIN*G3];       // [k][g]
__device__ float g_WtDecT[HH*HH];         // [k][g]
__device__ float g_WtEncT[HH*HH];         // [k][g]
__device__ float g_h[BB*HH];
__device__ float g_q[BB*HH];
__device__ float g_ctx[BB*HH];
__device__ float g_dec_in[BB*OUTD];

// ---------------- packed f32x2 helpers ----------------
__device__ __forceinline__ u64 pk2(float a, float b){
    u64 r; asm("mov.b64 %0,{%1,%2};" : "=l"(r) : "f"(a), "f"(b)); return r;
}
__device__ __forceinline__ void upk2(u64 v, float& a, float& b){
    asm("mov.b64 {%0,%1},%2;" : "=f"(a), "=f"(b) : "l"(v));
}
__device__ __forceinline__ u64 ffma2(u64 a, u64 b, u64 c){
    u64 d; asm("fma.rn.f32x2 %0,%1,%2,%3;" : "=l"(d) : "l"(a), "l"(b), "l"(c)); return d;
}

// ---------------- activations ----------------
// Precise (exp-based) versions: used inside GRU recurrences (error must not
// accumulate over 256 steps).
__device__ __forceinline__ float fast_sigmoid(float x){
    x = fminf(fmaxf(x, -30.f), 30.f);
    float e = __expf(-x);
    return __fdividef(1.f, 1.f + e);
}
__device__ __forceinline__ float fast_tanh(float x){
    x = fminf(fmaxf(x, -15.f), 15.f);
    float e = __expf(2.f * x);
    return __fdividef(e - 1.f, e + 1.f);
}
// Single-MUFU tanh (MUFU.TANH): used only in one-shot attention score paths.
__device__ __forceinline__ float mtanh(float x){
    float y; asm("tanh.approx.f32 %0, %1;" : "=f"(y) : "f"(x)); return y;
}

// ---------------- weight transposes ----------------
__global__ void prep_weights_kernel(const float* __restrict__ eWhh,
                                    const float* __restrict__ dWhh,
                                    const float* __restrict__ dWih,
                                    const float* __restrict__ Wt){
    int idx = blockIdx.x * 256 + threadIdx.x;
    if (idx < G3*HH){
        int g = idx / HH, k = idx - g*HH;
        g_WhhEnc4[(k >> 2)*(G3*4) + g*4 + (k & 3)] = eWhh[idx];
        g_WhhDecT[k*G3 + g] = dWhh[idx];
    }
    if (idx < G3*KIN){
        int g = idx / KIN, k = idx - g*KIN;
        g_WihDecT[k*G3 + g] = dWih[idx];
    }
    if (idx < HH*HH){
        int g = idx / HH, k = idx - g*HH;
        g_WtDecT[k*HH + g] = Wt[g*(2*HH) + k];
        g_WtEncT[k*HH + g] = Wt[g*(2*HH) + HH + k];
    }
}

// ---------------- agent attention -> timestep reprs (MUFU.TANH) ----------------
__global__ void __launch_bounds__(256) agent_attn_kernel(const float* __restrict__ x,
        const float* __restrict__ Wa, const float* __restrict__ ba,
        const float* __restrict__ va){
    __shared__ float sW[HH*3], sb[HH], sv[HH];
    int tid = threadIdx.x;
    for (int idx = tid; idx < HH*3; idx += 256) sW[idx] = Wa[idx];
    sb[tid] = ba[tid];
    sv[tid] = va[tid];
    __syncthreads();
    int bt = blockIdx.x * 256 + tid;
    float xf[9];
    #pragma unroll
    for (int f = 0; f < 9; f++) xf[f] = x[bt*9 + f];
    float s0 = 0.f, s1 = 0.f, s2 = 0.f;
    for (int h = 0; h < HH; h++){
        float w0 = sW[h*3], w1 = sW[h*3+1], w2 = sW[h*3+2];
        float bb_ = sb[h], v = sv[h];
        s0 += v * mtanh(w0*xf[0] + w1*xf[1] + w2*xf[2] + bb_);
        s1 += v * mtanh(w0*xf[3] + w1*xf[4] + w2*xf[5] + bb_);
        s2 += v * mtanh(w0*xf[6] + w1*xf[7] + w2*xf[8] + bb_);
    }
    float m  = fmaxf(s0, fmaxf(s1, s2));
    float e0 = __expf(s0 - m), e1 = __expf(s1 - m), e2 = __expf(s2 - m);
    float inv = __fdividef(1.f, e0 + e1 + e2);
    float a0 = e0*inv, a1 = e1*inv, a2 = e2*inv;
    #pragma unroll
    for (int f = 0; f < 3; f++)
        g_tr[bt*3 + f] = a0*xf[f] + a1*xf[3+f] + a2*xf[6+f];
}

// ---------------- encoder GRU: 512 threads, 2-way k-split, vector loads --------
__global__ void __launch_bounds__(512) encoder_kernel(const float* __restrict__ Wih,
        const float* __restrict__ bih, const float* __restrict__ bhh){
    const int b0  = blockIdx.x * NB;
    const int tid = threadIdx.x;
    const int j   = tid & 255;
    const int s   = tid >> 8;
    __shared__ alignas(16) float h_sm[NB][HH];   // [i][k]
    __shared__ float xs[NB*3];                   // [i*3 + f]
    __shared__ float ps[256][25];                // s=1 reduced partials (24 used)

    for (int idx = tid; idx < NB*HH; idx += 512)
        h_sm[idx >> 8][idx & 255] = 0.f;

    float wR[3] = {0,0,0}, wZ[3] = {0,0,0}, wN[3] = {0,0,0};
    float bR = 0.f, bZ = 0.f, biN = 0.f, bhN = 0.f;
    if (s == 0){
        #pragma unroll
        for (int f = 0; f < 3; f++){
            wR[f] = Wih[j*3 + f];
            wZ[f] = Wih[(j+256)*3 + f];
            wN[f] = Wih[(j+512)*3 + f];
        }
        bR  = bih[j]     + bhh[j];
        bZ  = bih[j+256] + bhh[j+256];
        biN = bih[j+512];
        bhN = bhh[j+512];
    }
    const int w0base = s << 5;
    float hnew[8];

    for (int t = 0; t < TT; t++){
        if (tid < NB*3){
            int i = tid / 3, f = tid - i*3;
            xs[tid] = g_tr[((b0+i)*TT + t)*3 + f];
        }
        __syncthreads();   // barrier A

        u64 aR[8], aZ[8], aN[8];
        #pragma unroll
        for (int i = 0; i < 8; i++){ aR[i] = 0ull; aZ[i] = 0ull; aN[i] = 0ull; }

        #pragma unroll 4
        for (int w = 0; w < 32; w++){
            const int slab = w0base + w;
            const ulonglong2* wq =
                (const ulonglong2*)(g_WhhEnc4 + (size_t)slab*(G3*4));
            ulonglong2 wr = wq[j];
            ulonglong2 wz = wq[j + 256];
            ulonglong2 wn = wq[j + 512];
            #pragma unroll
            for (int i = 0; i < 8; i++){
                ulonglong2 h2 = ((const ulonglong2*)(&h_sm[i][0]))[slab & 63];
                aR[i] = ffma2(wr.x, h2.x, aR[i]);
                aR[i] = ffma2(wr.y, h2.y, aR[i]);
                aZ[i] = ffma2(wz.x, h2.x, aZ[i]);
                aZ[i] = ffma2(wz.y, h2.y, aZ[i]);
                aN[i] = ffma2(wn.x, h2.x, aN[i]);
                aN[i] = ffma2(wn.y, h2.y, aN[i]);
            }
        }

        if (s == 1){
            #pragma unroll
            for (int i = 0; i < 8; i++){
                float lo, hi;
                upk2(aR[i], lo, hi); ps[j][i]      = lo + hi;
                upk2(aZ[i], lo, hi); ps[j][8 + i]  = lo + hi;
                upk2(aN[i], lo, hi); ps[j][16 + i] = lo + hi;
            }
        }
        __syncthreads();   // barrier B

        if (s == 0){
            #pragma unroll
            for (int i = 0; i < 8; i++){
                float lo, hi;
                float x0 = xs[i*3], x1 = xs[i*3+1], x2 = xs[i*3+2];
                upk2(aR[i], lo, hi);
                float r = lo + hi + ps[j][i]      + bR + wR[0]*x0 + wR[1]*x1 + wR[2]*x2;
                upk2(aZ[i], lo, hi);
                float z = lo + hi + ps[j][8 + i]  + bZ + wZ[0]*x0 + wZ[1]*x1 + wZ[2]*x2;
                upk2(aN[i], lo, hi);
                float nh = lo + hi + ps[j][16 + i] + bhN;
                float ni = biN + wN[0]*x0 + wN[1]*x1 + wN[2]*x2;
                float h_old = h_sm[i][j];
                float rr = fast_sigmoid(r);
                float zz = fast_sigmoid(z);
                float nn = fast_tanh(ni + rr*nh);
                hnew[i] = nn + zz*(h_old - nn);
            }
            #pragma unroll
            for (int i = 0; i < 8; i++){
                h_sm[i][j] = hnew[i];
                g_enc_out_bf[((b0+i)*TT + t)*HH + j] = __float2bfloat16(hnew[i]);
            }
        }
    }
    if (s == 0){
        #pragma unroll
        for (int i = 0; i < NB; i++)
            g_h[(b0+i)*HH + j] = hnew[i];
    }
}

// ---------------- enc_proj(bf16) = enc_out(bf16) @ WtEncT(fp32) ----------------
__global__ void __launch_bounds__(256) encproj_gemm_kernel(){
    __shared__ alignas(16) float AsT[16][68];
    __shared__ alignas(16) float Bs[16][64];
    const int tid = threadIdx.x;
    const int tx = tid & 15, ty = tid >> 4;
    const int bm = blockIdx.x, bn = blockIdx.y;
    float acc[4][4] = {};
    const int arow = tid >> 2, acol = (tid & 3) << 2;
    const int brow = tid >> 4, bcol = (tid & 15) << 2;
    const __nv_bfloat16* Ap = g_enc_out_bf + (bm*64 + arow)*HH + acol;
    const float* Bp = g_WtEncT + brow*HH + bn*64 + bcol;
    for (int k0 = 0; k0 < HH; k0 += 16){
        uint2 av = *reinterpret_cast<const uint2*>(Ap + k0);
        __nv_bfloat162 alo = *reinterpret_cast<__nv_bfloat162*>(&av.x);
        __nv_bfloat162 ahi = *reinterpret_cast<__nv_bfloat162*>(&av.y);
        float2 f0 = __bfloat1622float2(alo);
        float2 f1 = __bfloat1622float2(ahi);
        AsT[acol  ][arow] = f0.x;
        AsT[acol+1][arow] = f0.y;
        AsT[acol+2][arow] = f1.x;
        AsT[acol+3][arow] = f1.y;
        float4 bv = *reinterpret_cast<const float4*>(Bp + k0*HH);
        *reinterpret_cast<float4*>(&Bs[brow][bcol]) = bv;
        __syncthreads();
        #pragma unroll
        for (int kk = 0; kk < 16; kk++){
            float4 a4 = *reinterpret_cast<float4*>(&AsT[kk][ty*4]);
            float4 b4 = *reinterpret_cast<float4*>(&Bs[kk][tx*4]);
            float a[4] = {a4.x, a4.y, a4.z, a4.w};
            float b[4] = {b4.x, b4.y, b4.z, b4.w};
            #pragma unroll
            for (int i = 0; i < 4; i++)
                #pragma unroll
                for (int jj = 0; jj < 4; jj++) acc[i][jj] += a[i]*b[jj];
        }
        __syncthreads();
    }
    __nv_bfloat16* Cp = g_enc_proj_bf + (bm*64 + ty*4)*HH + bn*64 + tx*4;
    #pragma unroll
    for (int i = 0; i < 4; i++){
        __nv_bfloat162 c0 = __floats2bfloat162_rn(acc[i][0], acc[i][1]);
        __nv_bfloat162 c1 = __floats2bfloat162_rn(acc[i][2], acc[i][3]);
        *reinterpret_cast<__nv_bfloat162*>(Cp + i*HH)     = c0;
        *reinterpret_cast<__nv_bfloat162*>(Cp + i*HH + 2) = c1;
    }
}

// ---------------- decoder init ----------------
__global__ void dec_init_kernel(const float* __restrict__ x){
    int idx = blockIdx.x * 256 + threadIdx.x;
    if (idx < BB*OUTD){
        int b = idx / OUTD, f = idx - b*OUTD;
        g_dec_in[idx] = x[(b*TT + (TT-1))*9 + f];
    }
}

// q0 = h_enc @ WtDec^T + bt
__global__ void __launch_bounds__(256) compute_q0_kernel(const float* __restrict__ bt){
    const int b0 = blockIdx.x * NB;
    const int j = threadIdx.x;
    __shared__ float hs[NB*HH];
    for (int idx = j; idx < NB*HH; idx += 256) hs[idx] = g_h[b0*HH + idx];
    __syncthreads();
    float qa[NB];
    float btj = bt[j];
    #pragma unroll
    for (int i = 0; i < NB; i++) qa[i] = btj;
    const float* Wq = g_WtDecT + j;
    #pragma unroll 4
    for (int k = 0; k < HH; k++){
        float w = Wq[k*HH];
        #pragma unroll
        for (int i = 0; i < NB; i++) qa[i] += w * hs[i*HH + k];
    }
    #pragma unroll
    for (int i = 0; i < NB; i++) g_q[(b0+i)*HH + j] = qa[i];
}

// ---------------- decoder temporal attention + context (bf16, MUFU.TANH) -------
__global__ void __launch_bounds__(256) dec_attn_kernel(const float* __restrict__ vt){
    const int b = blockIdx.x, tid = threadIdx.x, w = tid >> 5, l = tid & 31;
    __shared__ alignas(16) float qs[HH];
    __shared__ alignas(16) float vs[HH];
    __shared__ float sc[TT], rb1[8], rb2[8];
    qs[tid] = g_q[b*HH + tid];
    vs[tid] = vt[tid];
    __syncthreads();

    float4 qA = *reinterpret_cast<float4*>(qs + l*8);
    float4 qB = *reinterpret_cast<float4*>(qs + l*8 + 4);
    float4 vA = *reinterpret_cast<float4*>(vs + l*8);
    float4 vB = *reinterpret_cast<float4*>(vs + l*8 + 4);
    float qr[8] = {qA.x,qA.y,qA.z,qA.w,qB.x,qB.y,qB.z,qB.w};
    float vr[8] = {vA.x,vA.y,vA.z,vA.w,vB.x,vB.y,vB.z,vB.w};

    for (int t = w; t < TT; t += 8){
        const __nv_bfloat16* ep = g_enc_proj_bf + (size_t)(b*TT + t)*HH + l*8;
        uint4 pv = *reinterpret_cast<const uint4*>(ep);
        float2 e0 = __bfloat1622float2(*reinterpret_cast<__nv_bfloat162*>(&pv.x));
        float2 e1 = __bfloat1622float2(*reinterpret_cast<__nv_bfloat162*>(&pv.y));
        float2 e2 = __bfloat1622float2(*reinterpret_cast<__nv_bfloat162*>(&pv.z));
        float2 e3 = __bfloat1622float2(*reinterpret_cast<__nv_bfloat162*>(&pv.w));
        float ef[8] = {e0.x,e0.y,e1.x,e1.y,e2.x,e2.y,e3.x,e3.y};
        float a = 0.f;
        #pragma unroll
        for (int u = 0; u < 8; u++)
            a += vr[u] * mtanh(ef[u] + qr[u]);
        #pragma unroll
        for (int o = 16; o; o >>= 1) a += __shfl_xor_sync(0xffffffffu, a, o);
        if (l == 0) sc[t] = a;
    }
    __syncthreads();
    float v = sc[tid];
    float m = v;
    #pragma unroll
    for (int o = 16; o; o >>= 1) m = fmaxf(m, __shfl_xor_sync(0xffffffffu, m, o));
    if (l == 0) rb1[w] = m;
    __syncthreads();
    m = rb1[0];
    #pragma unroll
    for (int i = 1; i < 8; i++) m = fmaxf(m, rb1[i]);
    float e = __expf(v - m);
    float s = e;
    #pragma unroll
    for (int o = 16; o; o >>= 1) s += __shfl_xor_sync(0xffffffffu, s, o);
    if (l == 0) rb2[w] = s;
    __syncthreads();
    s = 0.f;
    #pragma unroll
    for (int i = 0; i < 8; i++) s += rb2[i];
    sc[tid] = e * __fdividef(1.f, s);
    __syncthreads();
    float c = 0.f;
    const __nv_bfloat16* eo = g_enc_out_bf + (size_t)b*TT*HH + tid;
    #pragma unroll 8
    for (int t2 = 0; t2 < TT; t2++) c += sc[t2] * __bfloat162float(eo[t2*HH]);
    g_ctx[b*HH + tid] = c;
}

// ---------------- decoder GRU + prediction head + next-step q ----------------
__global__ void __launch_bounds__(256) dec_gru_kernel(const float* __restrict__ bih,
        const float* __restrict__ bhh, const float* __restrict__ bt,
        const float* __restrict__ Wfc, const float* __restrict__ bfc,
        float* __restrict__ out, int step){
    const int b0 = blockIdx.x * NB;
    const int j  = threadIdx.x;
    __shared__ alignas(16) float in_sm[KIN*NB];
    __shared__ alignas(16) float h_sm[HH*NB];
    __shared__ float hn_sm[NB*HH];

    for (int idx = j; idx < KIN*NB; idx += 256){
        int k = idx / NB, i = idx - k*NB;
        in_sm[idx] = (k < OUTD) ? g_dec_in[(b0+i)*OUTD + k]
                                : g_ctx[(b0+i)*HH + (k - OUTD)];
    }
    for (int idx = j; idx < HH*NB; idx += 256){
        int k = idx / NB, i = idx - k*NB;
        h_sm[idx] = g_h[(b0+i)*HH + k];
    }
    __syncthreads();

    u64 aR[4], aZ[4], aNi[4], aNh[4];
    {
        float bR = bih[j] + bhh[j];
        float bZ = bih[j+256] + bhh[j+256];
        float bi = bih[j+512], bh = bhh[j+512];
        #pragma unroll
        for (int p = 0; p < 4; p++){
            aR[p]  = pk2(bR, bR);
            aZ[p]  = pk2(bZ, bZ);
            aNi[p] = pk2(bi, bi);
            aNh[p] = pk2(bh, bh);
        }
    }
    const float* Wi = g_WihDecT + j;
    #pragma unroll 4
    for (int k = 0; k < KIN; k++){
        float wr = Wi[k*G3], wz = Wi[k*G3 + 256], wn = Wi[k*G3 + 512];
        u64 wr2 = pk2(wr, wr), wz2 = pk2(wz, wz), wn2 = pk2(wn, wn);
        const u64* ip = (const u64*)(in_sm + k*NB);
        #pragma unroll
        for (int p = 0; p < 4; p++){
            u64 v = ip[p];
            aR[p]  = ffma2(wr2, v, aR[p]);
            aZ[p]  = ffma2(wz2, v, aZ[p]);
            aNi[p] = ffma2(wn2, v, aNi[p]);
        }
    }
    const float* Wh = g_WhhDecT + j;
    #pragma unroll 4
    for (int k = 0; k < HH; k++){
        float wr = Wh[k*G3], wz = Wh[k*G3 + 256], wn = Wh[k*G3 + 512];
        u64 wr2 = pk2(wr, wr), wz2 = pk2(wz, wz), wn2 = pk2(wn, wn);
        const u64* hp = (const u64*)(h_sm + k*NB);
        #pragma unroll
        for (int p = 0; p < 4; p++){
            u64 v = hp[p];
            aR[p]  = ffma2(wr2, v, aR[p]);
            aZ[p]  = ffma2(wz2, v, aZ[p]);
            aNh[p] = ffma2(wn2, v, aNh[p]);
        }
    }

    float hnew[8];
    #pragma unroll
    for (int p = 0; p < 4; p++){
        float r0,r1,z0,z1,ni0,ni1,nh0,nh1;
        upk2(aR[p],  r0,  r1);
        upk2(aZ[p],  z0,  z1);
        upk2(aNi[p], ni0, ni1);
        upk2(aNh[p], nh0, nh1);
        float h0 = h_sm[j*NB + 2*p];
        float h1 = h_sm[j*NB + 2*p + 1];
        float rr0 = fast_sigmoid(r0), rr1 = fast_sigmoid(r1);
        float zz0 = fast_sigmoid(z0), zz1 = fast_sigmoid(z1);
        float nn0 = fast_tanh(ni0 + rr0*nh0);
        float nn1 = fast_tanh(ni1 + rr1*nh1);
        hnew[2*p]   = nn0 + zz0*(h0 - nn0);
        hnew[2*p+1] = nn1 + zz1*(h1 - nn1);
    }
    #pragma unroll
    for (int i = 0; i < NB; i++){
        g_h[(b0+i)*HH + j] = hnew[i];
        hn_sm[i*HH + j]    = hnew[i];
    }
    __syncthreads();

    // q for next step
    {
        float qa[NB];
        float btj = bt[j];
        #pragma unroll
        for (int i = 0; i < NB; i++) qa[i] = btj;
        const float* Wq = g_WtDecT + j;
        #pragma unroll 4
        for (int k = 0; k < HH; k++){
            float w = Wq[k*HH];
            #pragma unroll
            for (int i = 0; i < NB; i++) qa[i] += w * hn_sm[i*HH + k];
        }
        #pragma unroll
        for (int i = 0; i < NB; i++) g_q[(b0+i)*HH + j] = qa[i];
    }

    // prediction head: 8 rows x 9 outputs
    if (j < NB*OUTD){
        int i = j / OUTD, o = j - i*OUTD;
        float d = bfc[o];
        const float* wf = Wfc + o*HH;
        const float* hv = hn_sm + i*HH;
        #pragma unroll 4
        for (int k = 0; k < HH; k++) d += wf[k] * hv[k];
        out[((b0+i)*PRED + step)*OUTD + o] = d;
        g_dec_in[(b0+i)*OUTD + o] = d;
    }
}

// ---------------- launcher ----------------
extern "C" void kernel_launch(void* const* d_in, const int* in_sizes, int n_in,
                              void* d_out, int out_size){
    const float* x    = (const float*)d_in[0];
    const float* Wa   = (const float*)d_in[1];
    const float* ba   = (const float*)d_in[2];
    const float* va   = (const float*)d_in[3];
    const float* eWih = (const float*)d_in[4];
    const float* eWhh = (const float*)d_in[5];
    const float* ebih = (const float*)d_in[6];
    const float* ebhh = (const float*)d_in[7];
    const float* dWih = (const float*)d_in[8];
    const float* dWhh = (const float*)d_in[9];
    const float* dbih = (const float*)d_in[10];
    const float* dbhh = (const float*)d_in[11];
    const float* Wt   = (const float*)d_in[12];
    const float* bt   = (const float*)d_in[13];
    const float* vt   = (const float*)d_in[14];
    const float* Wfc  = (const float*)d_in[15];
    const float* bfc  = (const float*)d_in[16];
    float* out = (float*)d_out;

    prep_weights_kernel<<<(G3*KIN + 255)/256, 256>>>(eWhh, dWhh, dWih, Wt);
    agent_attn_kernel<<<BB*TT/256, 256>>>(x, Wa, ba, va);
    encoder_kernel<<<NBLK, 512>>>(eWih, ebih, ebhh);
    encproj_gemm_kernel<<<dim3(BB*TT/64, HH/64), 256>>>();
    dec_init_kernel<<<(BB*OUTD + 255)/256, 256>>>(x);
    compute_q0_kernel<<<NBLK, 256>>>(bt);
    for (int p = 0; p < PRED; p++){
        dec_attn_kernel<<<BB, 256>>>(vt);
        dec_gru_kernel<<<NBLK, 256>>>(dbih, dbhh, bt, Wfc, bfc, out, p);
    }
}